// round 14
// baseline (speedup 1.0000x reference)
#include <cuda_runtime.h>
#include <cuda_fp16.h>
#include <math.h>
#include <stdint.h>

// Problem dims
#define TT 512
#define BB 64
#define EE 512
#define HD 512
#define HH 1024
#define CC 16
#define START_TAG 14
#define STOP_TAG 15
#define NG 4096          // 2 dirs * 4 gates * HD
#define MROWS (TT*BB)    // 32768

// ---------------- scratch ------------------------------------------------------
__device__ float g_G [(size_t)MROWS * NG];
__device__ float g_H1[(size_t)MROWS * HH];
__device__ __half g_As[(size_t)MROWS * 3 * HH];          // fp16 3-slot split A
__device__ __half g_Ws[(size_t)NG * 3 * HH];             // fp16 3-slot split W_ih
__device__ __half g_Whsp[2][(size_t)2 * 2048 * 1536];    // per-layer split+reordered Whh
__device__ __half g_hsplit[2][2][64 * 1536];             // [parity][dir][b][k3]
__device__ float g_feats[(size_t)BB * TT * CC];

__device__ unsigned int g_dbar_count[2];
__device__ unsigned int g_dbar_gen[2];

__device__ __forceinline__ void grid_barrier_dir(int dir, int nblk) {
    __syncthreads();
    if (threadIdx.x == 0) {
        __threadfence();
        unsigned int gen = *(volatile unsigned int*)&g_dbar_gen[dir];
        if (atomicAdd(&g_dbar_count[dir], 1u) == (unsigned)(nblk - 1)) {
            g_dbar_count[dir] = 0;
            __threadfence();
            atomicAdd(&g_dbar_gen[dir], 1u);
        } else {
            unsigned int cur;
            do {
                asm volatile("ld.acquire.gpu.u32 %0, [%1];"
                             : "=r"(cur) : "l"(&g_dbar_gen[dir]));
            } while (cur == gen);
        }
    }
    __syncthreads();
}

__device__ __forceinline__ uint32_t smem_u32(const void* p) {
    uint32_t a;
    asm("{ .reg .u64 t; cvta.to.shared.u64 t, %1; cvt.u32.u64 %0, t; }"
        : "=r"(a) : "l"(p));
    return a;
}

// ---------------- embedding gather fused with fp16 split ------------------------
// writes A[m][3*EE] slots (a0, a0, a1) directly; no fp32 X0 roundtrip.
__global__ void embed_split_kernel(const int* __restrict__ sent,
                                   const float* __restrict__ emb,
                                   __half* __restrict__ As) {
    int m = blockIdx.x;          // t*B + b
    int t = m >> 6;
    int b = m & 63;
    int tok = sent[b * TT + t];
    float4 v = reinterpret_cast<const float4*>(emb + (size_t)tok * EE)[threadIdx.x];
    float f[4] = {v.x, v.y, v.z, v.w};
    __half a0[4], a1[4];
#pragma unroll
    for (int i = 0; i < 4; i++) {
        a0[i] = __float2half_rn(f[i]);
        a1[i] = __float2half_rn(f[i] - __half2float(a0[i]));
    }
    uint2 p0 = *reinterpret_cast<uint2*>(a0);
    uint2 p1 = *reinterpret_cast<uint2*>(a1);
    __half* base = As + (size_t)m * 3 * EE + threadIdx.x * 4;
    *reinterpret_cast<uint2*>(base)          = p0;
    *reinterpret_cast<uint2*>(base + EE)     = p0;
    *reinterpret_cast<uint2*>(base + 2 * EE) = p1;
}

// ---------------- fp32 -> 2-term fp16 split for W (3 slots: b0, b1, b0) --------
__global__ void splitW_kernel(const float* __restrict__ X,
                              __half* __restrict__ Y,
                              int K, long long total) {
    long long idx = (long long)blockIdx.x * blockDim.x + threadIdx.x;
    if (idx >= total) return;
    int m = (int)(idx / K);
    int k = (int)(idx % K);
    float a = X[idx];
    __half b0 = __float2half_rn(a);
    float r = a - __half2float(b0);
    __half b1 = __float2half_rn(r);
    __half* base = Y + (size_t)m * 3 * K + k;
    base[0 * K] = b0; base[1 * K] = b1; base[2 * K] = b0;
}

// ---------------- Whh -> split fp16 with gate-major row reorder -----------------
__global__ void splitWhh_kernel(const float* __restrict__ W,
                                __half* __restrict__ Y) {
    long long idx = (long long)blockIdx.x * blockDim.x + threadIdx.x;
    if (idx >= (long long)2 * 2048 * 512) return;
    int k = (int)(idx & 511);
    int row = (int)((idx >> 9) & 2047);
    int dir = (int)(idx >> 20);
    float a = W[idx];
    __half w0 = __float2half_rn(a);
    float r = a - __half2float(w0);
    __half w1 = __float2half_rn(r);
    int g = row >> 9;
    int u = row & 511;
    int rnew = (u >> 3) * 32 + g * 8 + (u & 7);
    __half* base = Y + ((size_t)dir * 2048 + rnew) * 1536 + k;
    base[0] = w0; base[512] = w1; base[1024] = w0;
}

// ---------------- mma / cp.async helpers ----------------------------------------
__device__ __forceinline__ void ldsm4(uint32_t addr, uint32_t r[4]) {
    asm volatile("ldmatrix.sync.aligned.m8n8.x4.shared.b16 {%0,%1,%2,%3}, [%4];"
                 : "=r"(r[0]), "=r"(r[1]), "=r"(r[2]), "=r"(r[3]) : "r"(addr));
}
__device__ __forceinline__ void ldsm2(uint32_t addr, uint32_t r[2]) {
    asm volatile("ldmatrix.sync.aligned.m8n8.x2.shared.b16 {%0,%1}, [%2];"
                 : "=r"(r[0]), "=r"(r[1]) : "r"(addr));
}
__device__ __forceinline__ void mma16816(float c[4], const uint32_t a[4],
                                         const uint32_t b[2]) {
    asm volatile(
        "mma.sync.aligned.m16n8k16.row.col.f32.f16.f16.f32 "
        "{%0,%1,%2,%3}, {%4,%5,%6,%7}, {%8,%9}, {%0,%1,%2,%3};"
        : "+f"(c[0]), "+f"(c[1]), "+f"(c[2]), "+f"(c[3])
        : "r"(a[0]), "r"(a[1]), "r"(a[2]), "r"(a[3]), "r"(b[0]), "r"(b[1]));
}
__device__ __forceinline__ void cp16(uint32_t dst, const void* src) {
    asm volatile("cp.async.cg.shared.global [%0], [%1], 16;" :: "r"(dst), "l"(src));
}
__device__ __forceinline__ void cp_commit() {
    asm volatile("cp.async.commit_group;");
}
template <int N>
__device__ __forceinline__ void cp_wait() {
    asm volatile("cp.async.wait_group %0;" :: "n"(N));
}

// ===== pipelined warp-mma fp16 GEMM: BM=128, BN=256, BK=64, 4 stages ===========
#define BM 128
#define BN 256
#define BK 64
#define NSTAGE 4
#define PADH 72
#define SA_BYTES (BM * PADH * 2)             // 18432
#define SB_BYTES (BN * PADH * 2)             // 36864
#define GEMM_SMEM (NSTAGE * (SA_BYTES + SB_BYTES))   // 221184

__global__ void __launch_bounds__(256, 1)
gemm_mma(const __half* __restrict__ A,
         const __half* __restrict__ W,
         const float* __restrict__ b1,
         const float* __restrict__ b2,
         float* __restrict__ C,
         int K3) {
    extern __shared__ char dsm[];
    const uint32_t sAb = smem_u32(dsm);
    const uint32_t sBb = sAb + NSTAGE * SA_BYTES;

    const int tid = threadIdx.x;
    const int lane = tid & 31;
    const int wid = tid >> 5;
    const int warpm = wid >> 2;     // 0..1
    const int warpn = wid & 3;      // 0..3
    const int n0 = blockIdx.x * BN;
    const int m0 = blockIdx.y * BM;

    const int rowoff = ((lane >> 3) & 1) * 8 + (lane & 7);
    const int koffA  = (lane >> 4) * 8;
    const int noff   = ((lane >> 4) << 3) + (lane & 7);
    const int koffB  = ((lane >> 3) & 1) * 8;

    float acc[4][8][4];
#pragma unroll
    for (int i = 0; i < 4; i++)
#pragma unroll
        for (int j = 0; j < 8; j++)
#pragma unroll
            for (int q = 0; q < 4; q++) acc[i][j][q] = 0.f;

    auto issue = [&](int stage, int kt) {
        const int kb = kt * BK;
        const uint32_t sa = sAb + stage * SA_BYTES;
        const uint32_t sb = sBb + stage * SB_BYTES;
#pragma unroll
        for (int q = 0; q < 4; q++) {
            int c = tid + q * 256;
            int r = c >> 3, c8 = c & 7;
            cp16(sa + (uint32_t)(r * PADH + c8 * 8) * 2,
                 A + (size_t)(m0 + r) * K3 + kb + c8 * 8);
        }
#pragma unroll
        for (int q = 0; q < 8; q++) {
            int c = tid + q * 256;
            int r = c >> 3, c8 = c & 7;
            cp16(sb + (uint32_t)(r * PADH + c8 * 8) * 2,
                 W + (size_t)(n0 + r) * K3 + kb + c8 * 8);
        }
    };

    issue(0, 0); cp_commit();
    issue(1, 1); cp_commit();
    issue(2, 2); cp_commit();

    const int nkt = K3 / BK;
    int stage = 0;
    for (int kt = 0; kt < nkt; kt++) {
        cp_wait<2>();
        __syncthreads();
        if (kt + 3 < nkt) {
            int ns = stage + 3; if (ns >= NSTAGE) ns -= NSTAGE;
            issue(ns, kt + 3);
        }
        cp_commit();

        const uint32_t sa = sAb + stage * SA_BYTES;
        const uint32_t sb = sBb + stage * SB_BYTES;
#pragma unroll
        for (int ks = 0; ks < 4; ks++) {
            uint32_t af[4][4];
            uint32_t bf[8][2];
#pragma unroll
            for (int mf = 0; mf < 4; mf++) {
                int mrow = warpm * 64 + mf * 16 + rowoff;
                ldsm4(sa + (uint32_t)(mrow * PADH + ks * 16 + koffA) * 2, af[mf]);
            }
#pragma unroll
            for (int p = 0; p < 4; p++) {
                uint32_t rr[4];
                int nrow = warpn * 64 + p * 16 + noff;
                ldsm4(sb + (uint32_t)(nrow * PADH + ks * 16 + koffB) * 2, rr);
                bf[2 * p][0] = rr[0];     bf[2 * p][1] = rr[1];
                bf[2 * p + 1][0] = rr[2]; bf[2 * p + 1][1] = rr[3];
            }
#pragma unroll
            for (int mf = 0; mf < 4; mf++)
#pragma unroll
                for (int nf = 0; nf < 8; nf++)
                    mma16816(acc[mf][nf], af[mf], bf[nf]);
        }
        if (++stage == NSTAGE) stage = 0;
    }

    // epilogue: fp32 + biases
#pragma unroll
    for (int nf = 0; nf < 8; nf++) {
        const int col = n0 + warpn * 64 + nf * 8 + (lane & 3) * 2;
        const float bx = b1[col] + b2[col];
        const float by = b1[col + 1] + b2[col + 1];
#pragma unroll
        for (int mf = 0; mf < 4; mf++) {
            const int row = m0 + warpm * 64 + mf * 16 + (lane >> 2);
            float2 v0 = make_float2(acc[mf][nf][0] + bx, acc[mf][nf][1] + by);
            float2 v1 = make_float2(acc[mf][nf][2] + bx, acc[mf][nf][3] + by);
            *reinterpret_cast<float2*>(C + (size_t)row * NG + col) = v0;
            *reinterpret_cast<float2*>(C + (size_t)(row + 8) * NG + col) = v1;
        }
    }
}

// ================= tensor-core persistent LSTM layer ============================
// grid (64, 2). 512 threads, 16 warps (warpm 0..3 x warpn=gate 0..3).
// If Aout != null: write split fp16 A rows for the NEXT layer's GEMM (layer 0).
// Else: write fp32 Hcat (layer 1, feeds linear).
#define LKC 256
#define LNC 6
#define LAPAD 264
#define LWPAD 1544
#define LW_OFF 0
#define LA_OFF 98816
#define LG_OFF (98816 + 101376)
#define LSTM_SMEM (LG_OFF + 8192)            // 208384

__global__ void __launch_bounds__(512, 1)
lstm_layer(const float* __restrict__ G,
           const __half* __restrict__ Wsp,
           const float* __restrict__ h0,
           const float* __restrict__ c0,
           __half* __restrict__ hsplit,
           float* __restrict__ Hcat,
           __half* __restrict__ Aout) {
    extern __shared__ char dsm[];
    const uint32_t sW = smem_u32(dsm) + LW_OFF;
    const uint32_t sA = smem_u32(dsm) + LA_OFF;
    float (*gs)[64][8] = reinterpret_cast<float(*)[64][8]>(dsm + LG_OFF);

    const int dir = blockIdx.y;
    const int nb = blockIdx.x;
    const int u0 = nb * 8;
    const int tid = threadIdx.x;
    const int lane = tid & 31;
    const int wid = tid >> 5;
    const int warpm = wid >> 2;          // 0..3 (16 rows each)
    const int warpn = wid & 3;           // gate

    {
        const __half* wsrc = Wsp + ((size_t)dir * 2048 + nb * 32) * 1536;
        for (int q = 0; q < 12; q++) {
            int id = tid + q * 512;
            int r = id / 192, c8 = id % 192;
            uint4 v = *reinterpret_cast<const uint4*>(wsrc + (size_t)r * 1536 + c8 * 8);
            *reinterpret_cast<uint4*>(dsm + LW_OFF + (r * LWPAD + c8 * 8) * 2) = v;
        }
    }

    const int cb = tid >> 3;
    const int cj = tid & 7;
    float cr = c0[(size_t)dir * BB * HD + cb * HD + u0 + cj];
    {
        float hv = h0[(size_t)dir * BB * HD + cb * HD + u0 + cj];
        __half v0 = __float2half_rn(hv);
        __half v1 = __float2half_rn(hv - __half2float(v0));
        __half* hp = hsplit + ((size_t)0 * 2 + dir) * 64 * 1536 + cb * 1536;
        hp[u0 + cj] = v0;
        hp[512 + u0 + cj] = v0;
        hp[1024 + u0 + cj] = v1;
    }
    grid_barrier_dir(dir, 64);

    const int rowoff = ((lane >> 3) & 1) * 8 + (lane & 7);
    const int koffA  = (lane >> 4) * 8;
    const int brow   = warpn * 8 + (lane & 7);
    const int koffB  = ((lane >> 3) & 1) * 8;

    for (int s = 0; s < TT; s++) {
        const int t = dir ? (TT - 1 - s) : s;
        const __half* hin = hsplit + ((size_t)(s & 1) * 2 + dir) * 64 * 1536;
        __half* hout = hsplit + ((size_t)((s + 1) & 1) * 2 + dir) * 64 * 1536;

        auto issueA = [&](int stg, int kc) {
#pragma unroll
            for (int q = 0; q < 4; q++) {
                int id = tid + q * 512;
                int r = id >> 5, c8 = id & 31;
                cp16(sA + stg * (64 * LAPAD * 2) + (uint32_t)(r * LAPAD + c8 * 8) * 2,
                     hin + (size_t)r * 1536 + kc * LKC + c8 * 8);
            }
        };

        issueA(0, 0); cp_commit();
        issueA(1, 1); cp_commit();

        float acc[4];
#pragma unroll
        for (int q = 0; q < 4; q++) acc[q] = 0.f;

        int stage = 0;
        for (int kc = 0; kc < LNC; kc++) {
            cp_wait<1>();
            __syncthreads();
            if (kc + 2 < LNC) {
                int ns = stage + 2; if (ns >= 3) ns -= 3;
                issueA(ns, kc + 2);
            }
            cp_commit();

            const uint32_t sa = sA + stage * (64 * LAPAD * 2);
#pragma unroll
            for (int ks = 0; ks < LKC / 16; ks++) {
                uint32_t bfr[2];
                ldsm2(sW + (uint32_t)(brow * LWPAD + kc * LKC + ks * 16 + koffB) * 2, bfr);
                uint32_t af[4];
                int mrow = warpm * 16 + rowoff;
                ldsm4(sa + (uint32_t)(mrow * LAPAD + ks * 16 + koffA) * 2, af);
                mma16816(acc, af, bfr);
            }
            if (++stage == 3) stage = 0;
        }

        {
            const int j0 = (lane & 3) * 2;
            const size_t gcol = (size_t)dir * 2048 + warpn * 512 + u0 + j0;
            int m1 = warpm * 16 + (lane >> 2);
            int m2 = m1 + 8;
            float2 g1 = *reinterpret_cast<const float2*>(
                &G[(size_t)(t * BB + m1) * NG + gcol]);
            float2 g2 = *reinterpret_cast<const float2*>(
                &G[(size_t)(t * BB + m2) * NG + gcol]);
            gs[warpn][m1][j0]     = acc[0] + g1.x;
            gs[warpn][m1][j0 + 1] = acc[1] + g1.y;
            gs[warpn][m2][j0]     = acc[2] + g2.x;
            gs[warpn][m2][j0 + 1] = acc[3] + g2.y;
        }
        __syncthreads();

        {
            float ig = gs[0][cb][cj];
            float fg = gs[1][cb][cj];
            float gg = gs[2][cb][cj];
            float og = gs[3][cb][cj];
            float si = 1.f / (1.f + expf(-ig));
            float sf = 1.f / (1.f + expf(-fg));
            float so = 1.f / (1.f + expf(-og));
            float cn = sf * cr + si * tanhf(gg);
            float hn = so * tanhf(cn);
            cr = cn;
            __half v0 = __float2half_rn(hn);
            __half v1 = __float2half_rn(hn - __half2float(v0));
            if (Aout) {
                // write next-layer split A: row t*BB+cb, slots at 0/HH/2HH
                __half* ap = Aout + (size_t)(t * BB + cb) * (3 * HH)
                                  + dir * HD + u0 + cj;
                ap[0]      = v0;
                ap[HH]     = v0;
                ap[2 * HH] = v1;
            } else {
                Hcat[(size_t)t * BB * HH + cb * HH + dir * HD + u0 + cj] = hn;
            }
            __half* hp = hout + (size_t)cb * 1536;
            hp[u0 + cj] = v0;
            hp[512 + u0 + cj] = v0;
            hp[1024 + u0 + cj] = v1;
        }
        grid_barrier_dir(dir, 64);
    }
}

// ---------------- final linear ---------------------------------------------------
__global__ void linear_feats(const float* __restrict__ H1,
                             const float* __restrict__ lw,
                             const float* __restrict__ lb,
                             float* __restrict__ feats) {
    int warp = (blockIdx.x * blockDim.x + threadIdx.x) >> 5;
    int lane = threadIdx.x & 31;
    if (warp >= MROWS) return;
    const float* hrow = H1 + (size_t)warp * HH;
    float acc[CC];
#pragma unroll
    for (int c = 0; c < CC; c++) acc[c] = 0.f;
    for (int k = lane; k < HH; k += 32) {
        float hv = hrow[k];
#pragma unroll
        for (int c = 0; c < CC; c++) acc[c] += hv * lw[c * HH + k];
    }
#pragma unroll
    for (int c = 0; c < CC; c++) {
        float v = acc[c];
#pragma unroll
        for (int o = 16; o; o >>= 1) v += __shfl_down_sync(0xffffffffu, v, o);
        if (lane == 0) {
            int t = warp >> 6, b = warp & 63;
            feats[((size_t)b * TT + t) * CC + c] = v + lb[c];
        }
    }
}

// ---------------- Viterbi decode --------------------------------------------------
__global__ void viterbi_kernel(const float* __restrict__ feats,
                               const float* __restrict__ trans,
                               float* __restrict__ out,
                               int write_scores, int write_paths, int path_off) {
    const int b = blockIdx.x;
    const int c = threadIdx.x;
    __shared__ unsigned char bp[TT][CC];

    float tr[CC];
#pragma unroll
    for (int p = 0; p < CC; p++) tr[p] = trans[c * CC + p];

    float fv = (c == START_TAG) ? 0.f : -10000.f;
    const float* f = feats + (size_t)b * TT * CC;

    for (int t = 0; t < TT; t++) {
        float best = -3.4e38f;
        int arg = 0;
#pragma unroll
        for (int p = 0; p < CC; p++) {
            float sc = __shfl_sync(0x0000ffffu, fv, p) + tr[p];
            if (sc > best) { best = sc; arg = p; }
        }
        bp[t][c] = (unsigned char)arg;
        fv = best + f[t * CC + c];
    }

    float term = fv + trans[STOP_TAG * CC + c];
    float bv = term;
    int bi = c;
#pragma unroll
    for (int o = 8; o; o >>= 1) {
        float ov = __shfl_down_sync(0x0000ffffu, bv, o);
        int oi = __shfl_down_sync(0x0000ffffu, bi, o);
        if (ov > bv || (ov == bv && oi < bi)) { bv = ov; bi = oi; }
    }
    bv = __shfl_sync(0x0000ffffu, bv, 0);
    bi = __shfl_sync(0x0000ffffu, bi, 0);

    if (c == 0) {
        if (write_scores) out[b] = bv;
        if (write_paths) {
            int tag = bi;
            for (int t = TT - 1; t >= 0; t--) {
                out[path_off + b * TT + t] = (float)tag;
                tag = bp[t][tag];
            }
        }
    }
}

// ---------------- launch -----------------------------------------------------------
extern "C" void kernel_launch(void* const* d_in, const int* in_sizes, int n_in,
                              void* d_out, int out_size) {
    const int*   sent    = (const int*)  d_in[0];
    const float* emb     = (const float*)d_in[1];
    const float* wih0    = (const float*)d_in[2];
    const float* whh0    = (const float*)d_in[3];
    const float* bih0    = (const float*)d_in[4];
    const float* bhh0    = (const float*)d_in[5];
    const float* wih1    = (const float*)d_in[6];
    const float* whh1    = (const float*)d_in[7];
    const float* bih1    = (const float*)d_in[8];
    const float* bhh1    = (const float*)d_in[9];
    const float* linw    = (const float*)d_in[10];
    const float* linb    = (const float*)d_in[11];
    const float* trans   = (const float*)d_in[12];
    const float* h0      = (const float*)d_in[13];
    const float* c0      = (const float*)d_in[14];

    float *pG, *pH1, *pfe;
    __half *pAs, *pWs, *pWh0, *pWh1, *phs;
    cudaGetSymbolAddress((void**)&pG,  g_G);
    cudaGetSymbolAddress((void**)&pH1, g_H1);
    cudaGetSymbolAddress((void**)&pfe, g_feats);
    cudaGetSymbolAddress((void**)&pAs, g_As);
    cudaGetSymbolAddress((void**)&pWs, g_Ws);
    cudaGetSymbolAddress((void**)&pWh0, g_Whsp);
    pWh1 = pWh0 + (size_t)2 * 2048 * 1536;
    cudaGetSymbolAddress((void**)&phs, g_hsplit);

    cudaFuncSetAttribute(gemm_mma, cudaFuncAttributeMaxDynamicSharedMemorySize,
                         GEMM_SMEM);
    cudaFuncSetAttribute(lstm_layer, cudaFuncAttributeMaxDynamicSharedMemorySize,
                         LSTM_SMEM);

    // 1) fused embedding gather + fp16 split -> g_As (K3 = 1536)
    embed_split_kernel<<<MROWS, 128>>>(sent, emb, pAs);

    // recurrent-weight splits (independent)
    {
        long long tWh = (long long)2 * 2048 * 512;
        splitWhh_kernel<<<(unsigned)((tWh + 255) / 256), 256>>>(whh0, pWh0);
        splitWhh_kernel<<<(unsigned)((tWh + 255) / 256), 256>>>(whh1, pWh1);
    }

    // 2) layer-0: W split + tensor GEMM (K3 = 1536)
    {
        long long tW = (long long)NG * EE;
        splitW_kernel<<<(unsigned)((tW + 255) / 256), 256>>>(wih0, pWs, EE, tW);
        gemm_mma<<<dim3(NG / BN, MROWS / BM), 256, GEMM_SMEM>>>(
            pAs, pWs, bih0, bhh0, pG, 3 * EE);
    }

    // 3) layer-0 recurrence: writes layer-1 split A directly into g_As
    lstm_layer<<<dim3(64, 2), 512, LSTM_SMEM>>>(pG, pWh0, h0, c0, phs,
                                                nullptr, pAs);

    // 4) layer-1: W split + tensor GEMM (K3 = 3072)
    {
        long long tW = (long long)NG * HH;
        splitW_kernel<<<(unsigned)((tW + 255) / 256), 256>>>(wih1, pWs, HH, tW);
        gemm_mma<<<dim3(NG / BN, MROWS / BM), 256, GEMM_SMEM>>>(
            pAs, pWs, bih1, bhh1, pG, 3 * HH);
    }

    // 5) layer-1 recurrence: writes fp32 H1 for the linear layer
    lstm_layer<<<dim3(64, 2), 512, LSTM_SMEM>>>(pG, pWh1,
                                                h0 + 2 * BB * HD, c0 + 2 * BB * HD,
                                                phs, pH1, nullptr);

    // 6) linear -> feats
    linear_feats<<<(MROWS * 32 + 255) / 256, 256>>>(pH1, linw, linb, pfe);

    // 7) Viterbi decode + output write
    float* out = (float*)d_out;
    int write_scores, write_paths, path_off;
    if (out_size >= BB + BB * TT) { write_scores = 1; write_paths = 1; path_off = BB; }
    else if (out_size == BB * TT) { write_scores = 0; write_paths = 1; path_off = 0; }
    else                          { write_scores = 1; write_paths = 0; path_off = 0; }
    viterbi_kernel<<<BB, CC>>>(pfe, trans, out, write_scores, write_paths, path_off);
}

// round 16
// speedup vs baseline: 1.1197x; 1.1197x over previous
#include <cuda_runtime.h>
#include <cuda_fp16.h>
#include <math.h>
#include <stdint.h>

// Problem dims
#define TT 512
#define BB 64
#define EE 512
#define HD 512
#define HH 1024
#define CC 16
#define START_TAG 14
#define STOP_TAG 15
#define NG 4096          // 2 dirs * 4 gates * HD
#define MROWS (TT*BB)    // 32768

// ---------------- scratch ------------------------------------------------------
__device__ float g_G [(size_t)MROWS * NG];
__device__ float g_H1[(size_t)MROWS * HH];
__device__ __half g_As[(size_t)MROWS * 3 * HH];          // fp16 3-slot split A (GEMM)
__device__ __half g_Ws[(size_t)NG * 3 * HH];             // fp16 3-slot split W_ih
__device__ __half g_Whsp[2][(size_t)2 * 2048 * 1536];    // per-layer split+reordered Whh
__device__ __half g_hsplit[2][2][64 * 1024];             // [parity][dir][b][(a0|a1)]
__device__ float g_feats[(size_t)BB * TT * CC];

__device__ unsigned int g_dbar_count[2];
__device__ unsigned int g_dbar_gen[2];

__device__ __forceinline__ void grid_barrier_dir(int dir, int nblk) {
    __syncthreads();
    if (threadIdx.x == 0) {
        __threadfence();
        unsigned int gen = *(volatile unsigned int*)&g_dbar_gen[dir];
        if (atomicAdd(&g_dbar_count[dir], 1u) == (unsigned)(nblk - 1)) {
            g_dbar_count[dir] = 0;
            __threadfence();
            atomicAdd(&g_dbar_gen[dir], 1u);
        } else {
            unsigned int cur;
            do {
                asm volatile("ld.acquire.gpu.u32 %0, [%1];"
                             : "=r"(cur) : "l"(&g_dbar_gen[dir]));
            } while (cur == gen);
        }
    }
    __syncthreads();
}

__device__ __forceinline__ uint32_t smem_u32(const void* p) {
    uint32_t a;
    asm("{ .reg .u64 t; cvta.to.shared.u64 t, %1; cvt.u32.u64 %0, t; }"
        : "=r"(a) : "l"(p));
    return a;
}

// ---------------- embedding gather fused with fp16 split (3-slot for GEMM) ------
__global__ void embed_split_kernel(const int* __restrict__ sent,
                                   const float* __restrict__ emb,
                                   __half* __restrict__ As) {
    int m = blockIdx.x;          // t*B + b
    int t = m >> 6;
    int b = m & 63;
    int tok = sent[b * TT + t];
    float4 v = reinterpret_cast<const float4*>(emb + (size_t)tok * EE)[threadIdx.x];
    float f[4] = {v.x, v.y, v.z, v.w};
    __half a0[4], a1[4];
#pragma unroll
    for (int i = 0; i < 4; i++) {
        a0[i] = __float2half_rn(f[i]);
        a1[i] = __float2half_rn(f[i] - __half2float(a0[i]));
    }
    uint2 p0 = *reinterpret_cast<uint2*>(a0);
    uint2 p1 = *reinterpret_cast<uint2*>(a1);
    __half* base = As + (size_t)m * 3 * EE + threadIdx.x * 4;
    *reinterpret_cast<uint2*>(base)          = p0;
    *reinterpret_cast<uint2*>(base + EE)     = p0;
    *reinterpret_cast<uint2*>(base + 2 * EE) = p1;
}

// ---------------- fp32 -> 2-term fp16 split for W (3 slots: b0, b1, b0) --------
__global__ void splitW_kernel(const float* __restrict__ X,
                              __half* __restrict__ Y,
                              int K, long long total) {
    long long idx = (long long)blockIdx.x * blockDim.x + threadIdx.x;
    if (idx >= total) return;
    int m = (int)(idx / K);
    int k = (int)(idx % K);
    float a = X[idx];
    __half b0 = __float2half_rn(a);
    float r = a - __half2float(b0);
    __half b1 = __float2half_rn(r);
    __half* base = Y + (size_t)m * 3 * K + k;
    base[0 * K] = b0; base[1 * K] = b1; base[2 * K] = b0;
}

// ---------------- Whh -> split fp16, gate-major reorder, [w0|w1|w0] rows --------
__global__ void splitWhh_kernel(const float* __restrict__ W,
                                __half* __restrict__ Y) {
    long long idx = (long long)blockIdx.x * blockDim.x + threadIdx.x;
    if (idx >= (long long)2 * 2048 * 512) return;
    int k = (int)(idx & 511);
    int row = (int)((idx >> 9) & 2047);
    int dir = (int)(idx >> 20);
    float a = W[idx];
    __half w0 = __float2half_rn(a);
    float r = a - __half2float(w0);
    __half w1 = __float2half_rn(r);
    int g = row >> 9;
    int u = row & 511;
    int rnew = (u >> 3) * 32 + g * 8 + (u & 7);
    __half* base = Y + ((size_t)dir * 2048 + rnew) * 1536 + k;
    base[0] = w0; base[512] = w1; base[1024] = w0;
}

// ---------------- mma / cp.async helpers ----------------------------------------
__device__ __forceinline__ void ldsm4(uint32_t addr, uint32_t r[4]) {
    asm volatile("ldmatrix.sync.aligned.m8n8.x4.shared.b16 {%0,%1,%2,%3}, [%4];"
                 : "=r"(r[0]), "=r"(r[1]), "=r"(r[2]), "=r"(r[3]) : "r"(addr));
}
__device__ __forceinline__ void ldsm2(uint32_t addr, uint32_t r[2]) {
    asm volatile("ldmatrix.sync.aligned.m8n8.x2.shared.b16 {%0,%1}, [%2];"
                 : "=r"(r[0]), "=r"(r[1]) : "r"(addr));
}
__device__ __forceinline__ void mma16816(float c[4], const uint32_t a[4],
                                         const uint32_t b[2]) {
    asm volatile(
        "mma.sync.aligned.m16n8k16.row.col.f32.f16.f16.f32 "
        "{%0,%1,%2,%3}, {%4,%5,%6,%7}, {%8,%9}, {%0,%1,%2,%3};"
        : "+f"(c[0]), "+f"(c[1]), "+f"(c[2]), "+f"(c[3])
        : "r"(a[0]), "r"(a[1]), "r"(a[2]), "r"(a[3]), "r"(b[0]), "r"(b[1]));
}
__device__ __forceinline__ void cp16(uint32_t dst, const void* src) {
    asm volatile("cp.async.cg.shared.global [%0], [%1], 16;" :: "r"(dst), "l"(src));
}
__device__ __forceinline__ void cp_commit() {
    asm volatile("cp.async.commit_group;");
}
template <int N>
__device__ __forceinline__ void cp_wait() {
    asm volatile("cp.async.wait_group %0;" :: "n"(N));
}

// ===== pipelined warp-mma fp16 GEMM: BM=128, BN=256, BK=64, 3 stages (R12) =====
#define BM 128
#define BN 256
#define BK 64
#define NSTAGE 3
#define PADH 72
#define SA_BYTES (BM * PADH * 2)
#define SB_BYTES (BN * PADH * 2)
#define GEMM_SMEM (NSTAGE * (SA_BYTES + SB_BYTES))   // 165888

__global__ void __launch_bounds__(256, 1)
gemm_mma(const __half* __restrict__ A,
         const __half* __restrict__ W,
         const float* __restrict__ b1,
         const float* __restrict__ b2,
         float* __restrict__ C,
         int K3) {
    extern __shared__ char dsm[];
    const uint32_t sAb = smem_u32(dsm);
    const uint32_t sBb = sAb + NSTAGE * SA_BYTES;

    const int tid = threadIdx.x;
    const int lane = tid & 31;
    const int wid = tid >> 5;
    const int warpm = wid >> 2;
    const int warpn = wid & 3;
    const int n0 = blockIdx.x * BN;
    const int m0 = blockIdx.y * BM;

    const int rowoff = ((lane >> 3) & 1) * 8 + (lane & 7);
    const int koffA  = (lane >> 4) * 8;
    const int noff   = ((lane >> 4) << 3) + (lane & 7);
    const int koffB  = ((lane >> 3) & 1) * 8;

    float acc[4][8][4];
#pragma unroll
    for (int i = 0; i < 4; i++)
#pragma unroll
        for (int j = 0; j < 8; j++)
#pragma unroll
            for (int q = 0; q < 4; q++) acc[i][j][q] = 0.f;

    auto issue = [&](int stage, int kt) {
        const int kb = kt * BK;
        const uint32_t sa = sAb + stage * SA_BYTES;
        const uint32_t sb = sBb + stage * SB_BYTES;
#pragma unroll
        for (int q = 0; q < 4; q++) {
            int c = tid + q * 256;
            int r = c >> 3, c8 = c & 7;
            cp16(sa + (uint32_t)(r * PADH + c8 * 8) * 2,
                 A + (size_t)(m0 + r) * K3 + kb + c8 * 8);
        }
#pragma unroll
        for (int q = 0; q < 8; q++) {
            int c = tid + q * 256;
            int r = c >> 3, c8 = c & 7;
            cp16(sb + (uint32_t)(r * PADH + c8 * 8) * 2,
                 W + (size_t)(n0 + r) * K3 + kb + c8 * 8);
        }
    };

    issue(0, 0); cp_commit();
    issue(1, 1); cp_commit();

    const int nkt = K3 / BK;
    int stage = 0;
    for (int kt = 0; kt < nkt; kt++) {
        cp_wait<1>();
        __syncthreads();
        if (kt + 2 < nkt) {
            int ns = stage + 2; if (ns >= NSTAGE) ns -= NSTAGE;
            issue(ns, kt + 2);
        }
        cp_commit();

        const uint32_t sa = sAb + stage * SA_BYTES;
        const uint32_t sb = sBb + stage * SB_BYTES;
#pragma unroll
        for (int ks = 0; ks < 4; ks++) {
            uint32_t af[4][4];
            uint32_t bf[8][2];
#pragma unroll
            for (int mf = 0; mf < 4; mf++) {
                int mrow = warpm * 64 + mf * 16 + rowoff;
                ldsm4(sa + (uint32_t)(mrow * PADH + ks * 16 + koffA) * 2, af[mf]);
            }
#pragma unroll
            for (int p = 0; p < 4; p++) {
                uint32_t rr[4];
                int nrow = warpn * 64 + p * 16 + noff;
                ldsm4(sb + (uint32_t)(nrow * PADH + ks * 16 + koffB) * 2, rr);
                bf[2 * p][0] = rr[0];     bf[2 * p][1] = rr[1];
                bf[2 * p + 1][0] = rr[2]; bf[2 * p + 1][1] = rr[3];
            }
#pragma unroll
            for (int mf = 0; mf < 4; mf++)
#pragma unroll
                for (int nf = 0; nf < 8; nf++)
                    mma16816(acc[mf][nf], af[mf], bf[nf]);
        }
        if (++stage == NSTAGE) stage = 0;
    }

#pragma unroll
    for (int nf = 0; nf < 8; nf++) {
        const int col = n0 + warpn * 64 + nf * 8 + (lane & 3) * 2;
        const float bx = b1[col] + b2[col];
        const float by = b1[col + 1] + b2[col + 1];
#pragma unroll
        for (int mf = 0; mf < 4; mf++) {
            const int row = m0 + warpm * 64 + mf * 16 + (lane >> 2);
            float2 v0 = make_float2(acc[mf][nf][0] + bx, acc[mf][nf][1] + by);
            float2 v1 = make_float2(acc[mf][nf][2] + bx, acc[mf][nf][3] + by);
            *reinterpret_cast<float2*>(C + (size_t)row * NG + col) = v0;
            *reinterpret_cast<float2*>(C + (size_t)(row + 8) * NG + col) = v1;
        }
    }
}

// ================= tensor-core persistent LSTM layer v2 =========================
// grid (64, 2). 512 threads, 16 warps (warpm 0..3 x warpn=gate 0..3).
// A (h split, 2 slots a0|a1 = 1024 halves/row) fully resident per step;
// W (w0|w1 = 1024 halves x 32 rows) persistent. Products: a0w0 + a0w1 + a1w0.
#define LWPAD2 1032
#define LAPAD2 1032
#define LW_OFF 0                                  // 32*1032*2  = 66048
#define LA_OFF 66048                              // 64*1032*2  = 132096
#define LG_OFF (66048 + 132096)                   // gs 8192
#define LSTM_SMEM (LG_OFF + 8192)                 // 206336

__global__ void __launch_bounds__(512, 1)
lstm_layer(const float* __restrict__ G,
           const __half* __restrict__ Wsp,   // [2][2048][1536] (w0|w1|w0 rows)
           const float* __restrict__ h0,
           const float* __restrict__ c0,
           __half* __restrict__ hsplit,      // [2][2][64*1024]
           float* __restrict__ Hcat,
           __half* __restrict__ Aout) {
    extern __shared__ char dsm[];
    const uint32_t sW = smem_u32(dsm) + LW_OFF;
    const uint32_t sA = smem_u32(dsm) + LA_OFF;
    float (*gs)[64][8] = reinterpret_cast<float(*)[64][8]>(dsm + LG_OFF);

    const int dir = blockIdx.y;
    const int nb = blockIdx.x;
    const int u0 = nb * 8;
    const int tid = threadIdx.x;
    const int lane = tid & 31;
    const int wid = tid >> 5;
    const int warpm = wid >> 2;          // 0..3 (16 rows each)
    const int warpn = wid & 3;           // gate

    // ---- load W slice: 32 rows x 1024 halves (w0|w1) into persistent smem ----
    {
        const __half* wsrc = Wsp + ((size_t)dir * 2048 + nb * 32) * 1536;
#pragma unroll
        for (int q = 0; q < 8; q++) {
            int id = tid + q * 512;              // 0..4095
            int r = id >> 7, c8 = id & 127;      // 128 8-half chunks per row
            uint4 v = *reinterpret_cast<const uint4*>(wsrc + (size_t)r * 1536 + c8 * 8);
            *reinterpret_cast<uint4*>(dsm + LW_OFF + (r * LWPAD2 + c8 * 8) * 2) = v;
        }
    }

    // ---- init: c->reg, split h0 into hsplit parity 0 (a0 at 0, a1 at 512) ----
    const int cb = tid >> 3;
    const int cj = tid & 7;
    float cr = c0[(size_t)dir * BB * HD + cb * HD + u0 + cj];
    {
        float hv = h0[(size_t)dir * BB * HD + cb * HD + u0 + cj];
        __half v0 = __float2half_rn(hv);
        __half v1 = __float2half_rn(hv - __half2float(v0));
        __half* hp = hsplit + ((size_t)0 * 2 + dir) * 64 * 1024 + cb * 1024;
        hp[u0 + cj] = v0;
        hp[512 + u0 + cj] = v1;
    }
    grid_barrier_dir(dir, 64);

    const int rowoff = ((lane >> 3) & 1) * 8 + (lane & 7);
    const int koffA  = (lane >> 4) * 8;
    const int brow   = warpn * 8 + (lane & 7);
    const int koffB  = ((lane >> 3) & 1) * 8;
    const int mrow   = warpm * 16 + rowoff;

    for (int s = 0; s < TT; s++) {
        const int t = dir ? (TT - 1 - s) : s;
        const __half* hin = hsplit + ((size_t)(s & 1) * 2 + dir) * 64 * 1024;
        __half* hout = hsplit + ((size_t)((s + 1) & 1) * 2 + dir) * 64 * 1024;

        // issue A slot (512 halves x 64 rows = 4096 8-half chunks; 8 per thread)
        auto issueA = [&](int half) {
#pragma unroll
            for (int q = 0; q < 8; q++) {
                int id = tid + q * 512;          // 0..4095
                int r = id >> 6, c8 = id & 63;   // 64 rows x 64 chunks
                cp16(sA + (uint32_t)(r * LAPAD2 + half * 512 + c8 * 8) * 2,
                     hin + (size_t)r * 1024 + half * 512 + c8 * 8);
            }
        };
        issueA(0); cp_commit();
        issueA(1); cp_commit();

        float acc[4];
#pragma unroll
        for (int q = 0; q < 4; q++) acc[q] = 0.f;

        // phase 1: a0 ready -> acc += a0*w0 + a0*w1
        cp_wait<1>();
        __syncthreads();
#pragma unroll
        for (int ks = 0; ks < 32; ks++) {
            uint32_t af[4];
            ldsm4(sA + (uint32_t)(mrow * LAPAD2 + ks * 16 + koffA) * 2, af);
            uint32_t w0f[2], w1f[2];
            ldsm2(sW + (uint32_t)(brow * LWPAD2 + ks * 16 + koffB) * 2, w0f);
            ldsm2(sW + (uint32_t)(brow * LWPAD2 + 512 + ks * 16 + koffB) * 2, w1f);
            mma16816(acc, af, w0f);
            mma16816(acc, af, w1f);
        }

        // phase 2: a1 ready -> acc += a1*w0
        cp_wait<0>();
        __syncthreads();
#pragma unroll
        for (int ks = 0; ks < 32; ks++) {
            uint32_t af[4];
            ldsm4(sA + (uint32_t)(mrow * LAPAD2 + 512 + ks * 16 + koffA) * 2, af);
            uint32_t w0f[2];
            ldsm2(sW + (uint32_t)(brow * LWPAD2 + ks * 16 + koffB) * 2, w0f);
            mma16816(acc, af, w0f);
        }

        // add G and stage gates in smem (warpn == gate)
        {
            const int j0 = (lane & 3) * 2;
            const size_t gcol = (size_t)dir * 2048 + warpn * 512 + u0 + j0;
            int m1 = warpm * 16 + (lane >> 2);
            int m2 = m1 + 8;
            float2 g1 = *reinterpret_cast<const float2*>(
                &G[(size_t)(t * BB + m1) * NG + gcol]);
            float2 g2 = *reinterpret_cast<const float2*>(
                &G[(size_t)(t * BB + m2) * NG + gcol]);
            gs[warpn][m1][j0]     = acc[0] + g1.x;
            gs[warpn][m1][j0 + 1] = acc[1] + g1.y;
            gs[warpn][m2][j0]     = acc[2] + g2.x;
            gs[warpn][m2][j0 + 1] = acc[3] + g2.y;
        }
        __syncthreads();

        // cell update: thread -> (batch cb, unit cj)
        {
            float ig = gs[0][cb][cj];
            float fg = gs[1][cb][cj];
            float gg = gs[2][cb][cj];
            float og = gs[3][cb][cj];
            float si = 1.f / (1.f + expf(-ig));
            float sf = 1.f / (1.f + expf(-fg));
            float so = 1.f / (1.f + expf(-og));
            float cn = sf * cr + si * tanhf(gg);
            float hn = so * tanhf(cn);
            cr = cn;
            __half v0 = __float2half_rn(hn);
            __half v1 = __float2half_rn(hn - __half2float(v0));
            if (Aout) {
                __half* ap = Aout + (size_t)(t * BB + cb) * (3 * HH)
                                  + dir * HD + u0 + cj;
                ap[0]      = v0;
                ap[HH]     = v0;
                ap[2 * HH] = v1;
            } else {
                Hcat[(size_t)t * BB * HH + cb * HH + dir * HD + u0 + cj] = hn;
            }
            __half* hp = hout + (size_t)cb * 1024;
            hp[u0 + cj] = v0;
            hp[512 + u0 + cj] = v1;
        }
        grid_barrier_dir(dir, 64);
    }
}

// ---------------- final linear ---------------------------------------------------
__global__ void linear_feats(const float* __restrict__ H1,
                             const float* __restrict__ lw,
                             const float* __restrict__ lb,
                             float* __restrict__ feats) {
    int warp = (blockIdx.x * blockDim.x + threadIdx.x) >> 5;
    int lane = threadIdx.x & 31;
    if (warp >= MROWS) return;
    const float* hrow = H1 + (size_t)warp * HH;
    float acc[CC];
#pragma unroll
    for (int c = 0; c < CC; c++) acc[c] = 0.f;
    for (int k = lane; k < HH; k += 32) {
        float hv = hrow[k];
#pragma unroll
        for (int c = 0; c < CC; c++) acc[c] += hv * lw[c * HH + k];
    }
#pragma unroll
    for (int c = 0; c < CC; c++) {
        float v = acc[c];
#pragma unroll
        for (int o = 16; o; o >>= 1) v += __shfl_down_sync(0xffffffffu, v, o);
        if (lane == 0) {
            int t = warp >> 6, b = warp & 63;
            feats[((size_t)b * TT + t) * CC + c] = v + lb[c];
        }
    }
}

// ---------------- Viterbi decode --------------------------------------------------
__global__ void viterbi_kernel(const float* __restrict__ feats,
                               const float* __restrict__ trans,
                               float* __restrict__ out,
                               int write_scores, int write_paths, int path_off) {
    const int b = blockIdx.x;
    const int c = threadIdx.x;
    __shared__ unsigned char bp[TT][CC];

    float tr[CC];
#pragma unroll
    for (int p = 0; p < CC; p++) tr[p] = trans[c * CC + p];

    float fv = (c == START_TAG) ? 0.f : -10000.f;
    const float* f = feats + (size_t)b * TT * CC;

    for (int t = 0; t < TT; t++) {
        float best = -3.4e38f;
        int arg = 0;
#pragma unroll
        for (int p = 0; p < CC; p++) {
            float sc = __shfl_sync(0x0000ffffu, fv, p) + tr[p];
            if (sc > best) { best = sc; arg = p; }
        }
        bp[t][c] = (unsigned char)arg;
        fv = best + f[t * CC + c];
    }

    float term = fv + trans[STOP_TAG * CC + c];
    float bv = term;
    int bi = c;
#pragma unroll
    for (int o = 8; o; o >>= 1) {
        float ov = __shfl_down_sync(0x0000ffffu, bv, o);
        int oi = __shfl_down_sync(0x0000ffffu, bi, o);
        if (ov > bv || (ov == bv && oi < bi)) { bv = ov; bi = oi; }
    }
    bv = __shfl_sync(0x0000ffffu, bv, 0);
    bi = __shfl_sync(0x0000ffffu, bi, 0);

    if (c == 0) {
        if (write_scores) out[b] = bv;
        if (write_paths) {
            int tag = bi;
            for (int t = TT - 1; t >= 0; t--) {
                out[path_off + b * TT + t] = (float)tag;
                tag = bp[t][tag];
            }
        }
    }
}

// ---------------- launch -----------------------------------------------------------
extern "C" void kernel_launch(void* const* d_in, const int* in_sizes, int n_in,
                              void* d_out, int out_size) {
    const int*   sent    = (const int*)  d_in[0];
    const float* emb     = (const float*)d_in[1];
    const float* wih0    = (const float*)d_in[2];
    const float* whh0    = (const float*)d_in[3];
    const float* bih0    = (const float*)d_in[4];
    const float* bhh0    = (const float*)d_in[5];
    const float* wih1    = (const float*)d_in[6];
    const float* whh1    = (const float*)d_in[7];
    const float* bih1    = (const float*)d_in[8];
    const float* bhh1    = (const float*)d_in[9];
    const float* linw    = (const float*)d_in[10];
    const float* linb    = (const float*)d_in[11];
    const float* trans   = (const float*)d_in[12];
    const float* h0      = (const float*)d_in[13];
    const float* c0      = (const float*)d_in[14];

    float *pG, *pH1, *pfe;
    __half *pAs, *pWs, *pWh0, *pWh1, *phs;
    cudaGetSymbolAddress((void**)&pG,  g_G);
    cudaGetSymbolAddress((void**)&pH1, g_H1);
    cudaGetSymbolAddress((void**)&pfe, g_feats);
    cudaGetSymbolAddress((void**)&pAs, g_As);
    cudaGetSymbolAddress((void**)&pWs, g_Ws);
    cudaGetSymbolAddress((void**)&pWh0, g_Whsp);
    pWh1 = pWh0 + (size_t)2 * 2048 * 1536;
    cudaGetSymbolAddress((void**)&phs, g_hsplit);

    cudaFuncSetAttribute(gemm_mma, cudaFuncAttributeMaxDynamicSharedMemorySize,
                         GEMM_SMEM);
    cudaFuncSetAttribute(lstm_layer, cudaFuncAttributeMaxDynamicSharedMemorySize,
                         LSTM_SMEM);

    // 1) fused embedding gather + fp16 split -> g_As (K3 = 1536)
    embed_split_kernel<<<MROWS, 128>>>(sent, emb, pAs);

    // recurrent-weight splits
    {
        long long tWh = (long long)2 * 2048 * 512;
        splitWhh_kernel<<<(unsigned)((tWh + 255) / 256), 256>>>(whh0, pWh0);
        splitWhh_kernel<<<(unsigned)((tWh + 255) / 256), 256>>>(whh1, pWh1);
    }

    // 2) layer-0: W split + tensor GEMM (K3 = 1536)
    {
        long long tW = (long long)NG * EE;
        splitW_kernel<<<(unsigned)((tW + 255) / 256), 256>>>(wih0, pWs, EE, tW);
        gemm_mma<<<dim3(NG / BN, MROWS / BM), 256, GEMM_SMEM>>>(
            pAs, pWs, bih0, bhh0, pG, 3 * EE);
    }

    // 3) layer-0 recurrence: writes layer-1 split A directly into g_As
    lstm_layer<<<dim3(64, 2), 512, LSTM_SMEM>>>(pG, pWh0, h0, c0, phs,
                                                nullptr, pAs);

    // 4) layer-1: W split + tensor GEMM (K3 = 3072)
    {
        long long tW = (long long)NG * HH;
        splitW_kernel<<<(unsigned)((tW + 255) / 256), 256>>>(wih1, pWs, HH, tW);
        gemm_mma<<<dim3(NG / BN, MROWS / BM), 256, GEMM_SMEM>>>(
            pAs, pWs, bih1, bhh1, pG, 3 * HH);
    }

    // 5) layer-1 recurrence: writes fp32 H1 for the linear layer
    lstm_layer<<<dim3(64, 2), 512, LSTM_SMEM>>>(pG, pWh1,
                                                h0 + 2 * BB * HD, c0 + 2 * BB * HD,
                                                phs, pH1, nullptr);

    // 6) linear -> feats
    linear_feats<<<(MROWS * 32 + 255) / 256, 256>>>(pH1, linw, linb, pfe);

    // 7) Viterbi decode + output write
    float* out = (float*)d_out;
    int write_scores, write_paths, path_off;
    if (out_size >= BB + BB * TT) { write_scores = 1; write_paths = 1; path_off = BB; }
    else if (out_size == BB * TT) { write_scores = 0; write_paths = 1; path_off = 0; }
    else                          { write_scores = 1; write_paths = 0; path_off = 0; }
    viterbi_kernel<<<BB, CC>>>(pfe, trans, out, write_scores, write_paths, path_off);
}

// round 17
// speedup vs baseline: 1.1570x; 1.0333x over previous
#include <cuda_runtime.h>
#include <cuda_fp16.h>
#include <math.h>
#include <stdint.h>

// Problem dims
#define TT 512
#define BB 64
#define EE 512
#define HD 512
#define HH 1024
#define CC 16
#define START_TAG 14
#define STOP_TAG 15
#define NG 4096          // 2 dirs * 4 gates * HD
#define MROWS (TT*BB)    // 32768

// ---------------- scratch ------------------------------------------------------
__device__ float g_G [(size_t)MROWS * NG];
__device__ float g_H1[(size_t)MROWS * HH];
__device__ __half g_As[(size_t)MROWS * 3 * HH];          // fp16 3-slot split A (GEMM)
__device__ __half g_Ws[(size_t)NG * 3 * HH];             // fp16 3-slot split W_ih
__device__ __half g_Whsp[2][(size_t)2 * 2048 * 1536];    // per-layer split+reordered Whh
__device__ __half g_hsplit[2][2][64 * 1024];             // [parity][dir][b][(a0|a1)]
__device__ float g_feats[(size_t)BB * TT * CC];

__device__ unsigned int g_dbar_count[2];
__device__ unsigned int g_dbar_gen[2];

__device__ __forceinline__ void grid_barrier_dir(int dir, int nblk) {
    __syncthreads();
    if (threadIdx.x == 0) {
        __threadfence();
        unsigned int gen = *(volatile unsigned int*)&g_dbar_gen[dir];
        if (atomicAdd(&g_dbar_count[dir], 1u) == (unsigned)(nblk - 1)) {
            g_dbar_count[dir] = 0;
            __threadfence();
            atomicAdd(&g_dbar_gen[dir], 1u);
        } else {
            unsigned int cur;
            do {
                asm volatile("ld.acquire.gpu.u32 %0, [%1];"
                             : "=r"(cur) : "l"(&g_dbar_gen[dir]));
            } while (cur == gen);
        }
    }
    __syncthreads();
}

__device__ __forceinline__ uint32_t smem_u32(const void* p) {
    uint32_t a;
    asm("{ .reg .u64 t; cvta.to.shared.u64 t, %1; cvt.u32.u64 %0, t; }"
        : "=r"(a) : "l"(p));
    return a;
}

// ---------------- embedding gather fused with fp16 split (3-slot for GEMM) ------
__global__ void embed_split_kernel(const int* __restrict__ sent,
                                   const float* __restrict__ emb,
                                   __half* __restrict__ As) {
    int m = blockIdx.x;          // t*B + b
    int t = m >> 6;
    int b = m & 63;
    int tok = sent[b * TT + t];
    float4 v = reinterpret_cast<const float4*>(emb + (size_t)tok * EE)[threadIdx.x];
    float f[4] = {v.x, v.y, v.z, v.w};
    __half a0[4], a1[4];
#pragma unroll
    for (int i = 0; i < 4; i++) {
        a0[i] = __float2half_rn(f[i]);
        a1[i] = __float2half_rn(f[i] - __half2float(a0[i]));
    }
    uint2 p0 = *reinterpret_cast<uint2*>(a0);
    uint2 p1 = *reinterpret_cast<uint2*>(a1);
    __half* base = As + (size_t)m * 3 * EE + threadIdx.x * 4;
    *reinterpret_cast<uint2*>(base)          = p0;
    *reinterpret_cast<uint2*>(base + EE)     = p0;
    *reinterpret_cast<uint2*>(base + 2 * EE) = p1;
}

// ---------------- fp32 -> 2-term fp16 split for W (3 slots: b0, b1, b0) --------
__global__ void splitW_kernel(const float* __restrict__ X,
                              __half* __restrict__ Y,
                              int K, long long total) {
    long long idx = (long long)blockIdx.x * blockDim.x + threadIdx.x;
    if (idx >= total) return;
    int m = (int)(idx / K);
    int k = (int)(idx % K);
    float a = X[idx];
    __half b0 = __float2half_rn(a);
    float r = a - __half2float(b0);
    __half b1 = __float2half_rn(r);
    __half* base = Y + (size_t)m * 3 * K + k;
    base[0 * K] = b0; base[1 * K] = b1; base[2 * K] = b0;
}

// ---------------- Whh -> split fp16, gate-major reorder, [w0|w1|w0] rows --------
__global__ void splitWhh_kernel(const float* __restrict__ W,
                                __half* __restrict__ Y) {
    long long idx = (long long)blockIdx.x * blockDim.x + threadIdx.x;
    if (idx >= (long long)2 * 2048 * 512) return;
    int k = (int)(idx & 511);
    int row = (int)((idx >> 9) & 2047);
    int dir = (int)(idx >> 20);
    float a = W[idx];
    __half w0 = __float2half_rn(a);
    float r = a - __half2float(w0);
    __half w1 = __float2half_rn(r);
    int g = row >> 9;
    int u = row & 511;
    int rnew = (u >> 3) * 32 + g * 8 + (u & 7);
    __half* base = Y + ((size_t)dir * 2048 + rnew) * 1536 + k;
    base[0] = w0; base[512] = w1; base[1024] = w0;
}

// ---------------- mma / cp.async helpers ----------------------------------------
__device__ __forceinline__ void ldsm4(uint32_t addr, uint32_t r[4]) {
    asm volatile("ldmatrix.sync.aligned.m8n8.x4.shared.b16 {%0,%1,%2,%3}, [%4];"
                 : "=r"(r[0]), "=r"(r[1]), "=r"(r[2]), "=r"(r[3]) : "r"(addr));
}
__device__ __forceinline__ void mma16816(float c[4], const uint32_t a[4],
                                         const uint32_t b[2]) {
    asm volatile(
        "mma.sync.aligned.m16n8k16.row.col.f32.f16.f16.f32 "
        "{%0,%1,%2,%3}, {%4,%5,%6,%7}, {%8,%9}, {%0,%1,%2,%3};"
        : "+f"(c[0]), "+f"(c[1]), "+f"(c[2]), "+f"(c[3])
        : "r"(a[0]), "r"(a[1]), "r"(a[2]), "r"(a[3]), "r"(b[0]), "r"(b[1]));
}
__device__ __forceinline__ void cp16(uint32_t dst, const void* src) {
    asm volatile("cp.async.cg.shared.global [%0], [%1], 16;" :: "r"(dst), "l"(src));
}
__device__ __forceinline__ void cp_commit() {
    asm volatile("cp.async.commit_group;");
}
template <int N>
__device__ __forceinline__ void cp_wait() {
    asm volatile("cp.async.wait_group %0;" :: "n"(N));
}

// ===== pipelined warp-mma fp16 GEMM: BM=128, BN=256, BK=64, 3 stages (R12) =====
#define BM 128
#define BN 256
#define BK 64
#define NSTAGE 3
#define PADH 72
#define SA_BYTES (BM * PADH * 2)
#define SB_BYTES (BN * PADH * 2)
#define GEMM_SMEM (NSTAGE * (SA_BYTES + SB_BYTES))   // 165888

__global__ void __launch_bounds__(256, 1)
gemm_mma(const __half* __restrict__ A,
         const __half* __restrict__ W,
         const float* __restrict__ b1,
         const float* __restrict__ b2,
         float* __restrict__ C,
         int K3) {
    extern __shared__ char dsm[];
    const uint32_t sAb = smem_u32(dsm);
    const uint32_t sBb = sAb + NSTAGE * SA_BYTES;

    const int tid = threadIdx.x;
    const int lane = tid & 31;
    const int wid = tid >> 5;
    const int warpm = wid >> 2;
    const int warpn = wid & 3;
    const int n0 = blockIdx.x * BN;
    const int m0 = blockIdx.y * BM;

    const int rowoff = ((lane >> 3) & 1) * 8 + (lane & 7);
    const int koffA  = (lane >> 4) * 8;
    const int noff   = ((lane >> 4) << 3) + (lane & 7);
    const int koffB  = ((lane >> 3) & 1) * 8;

    float acc[4][8][4];
#pragma unroll
    for (int i = 0; i < 4; i++)
#pragma unroll
        for (int j = 0; j < 8; j++)
#pragma unroll
            for (int q = 0; q < 4; q++) acc[i][j][q] = 0.f;

    auto issue = [&](int stage, int kt) {
        const int kb = kt * BK;
        const uint32_t sa = sAb + stage * SA_BYTES;
        const uint32_t sb = sBb + stage * SB_BYTES;
#pragma unroll
        for (int q = 0; q < 4; q++) {
            int c = tid + q * 256;
            int r = c >> 3, c8 = c & 7;
            cp16(sa + (uint32_t)(r * PADH + c8 * 8) * 2,
                 A + (size_t)(m0 + r) * K3 + kb + c8 * 8);
        }
#pragma unroll
        for (int q = 0; q < 8; q++) {
            int c = tid + q * 256;
            int r = c >> 3, c8 = c & 7;
            cp16(sb + (uint32_t)(r * PADH + c8 * 8) * 2,
                 W + (size_t)(n0 + r) * K3 + kb + c8 * 8);
        }
    };

    issue(0, 0); cp_commit();
    issue(1, 1); cp_commit();

    const int nkt = K3 / BK;
    int stage = 0;
    for (int kt = 0; kt < nkt; kt++) {
        cp_wait<1>();
        __syncthreads();
        if (kt + 2 < nkt) {
            int ns = stage + 2; if (ns >= NSTAGE) ns -= NSTAGE;
            issue(ns, kt + 2);
        }
        cp_commit();

        const uint32_t sa = sAb + stage * SA_BYTES;
        const uint32_t sb = sBb + stage * SB_BYTES;
#pragma unroll
        for (int ks = 0; ks < 4; ks++) {
            uint32_t af[4][4];
            uint32_t bf[8][2];
#pragma unroll
            for (int mf = 0; mf < 4; mf++) {
                int mrow = warpm * 64 + mf * 16 + rowoff;
                ldsm4(sa + (uint32_t)(mrow * PADH + ks * 16 + koffA) * 2, af[mf]);
            }
#pragma unroll
            for (int p = 0; p < 4; p++) {
                uint32_t rr[4];
                int nrow = warpn * 64 + p * 16 + noff;
                ldsm4(sb + (uint32_t)(nrow * PADH + ks * 16 + koffB) * 2, rr);
                bf[2 * p][0] = rr[0];     bf[2 * p][1] = rr[1];
                bf[2 * p + 1][0] = rr[2]; bf[2 * p + 1][1] = rr[3];
            }
#pragma unroll
            for (int mf = 0; mf < 4; mf++)
#pragma unroll
                for (int nf = 0; nf < 8; nf++)
                    mma16816(acc[mf][nf], af[mf], bf[nf]);
        }
        if (++stage == NSTAGE) stage = 0;
    }

#pragma unroll
    for (int nf = 0; nf < 8; nf++) {
        const int col = n0 + warpn * 64 + nf * 8 + (lane & 3) * 2;
        const float bx = b1[col] + b2[col];
        const float by = b1[col + 1] + b2[col + 1];
#pragma unroll
        for (int mf = 0; mf < 4; mf++) {
            const int row = m0 + warpm * 64 + mf * 16 + (lane >> 2);
            float2 v0 = make_float2(acc[mf][nf][0] + bx, acc[mf][nf][1] + by);
            float2 v1 = make_float2(acc[mf][nf][2] + bx, acc[mf][nf][3] + by);
            *reinterpret_cast<float2*>(C + (size_t)row * NG + col) = v0;
            *reinterpret_cast<float2*>(C + (size_t)(row + 8) * NG + col) = v1;
        }
    }
}

// ================= tensor-core persistent LSTM layer v3 =========================
// Same structure as R16; changes: (1) B fragments loaded in pairs via ldsm4
// (phase1: w0|w1 together; phase2: ks,ks+1 together), (2) G loads hoisted to
// step start so their latency hides behind the mma phases.
#define LWPAD2 1032
#define LAPAD2 1032
#define LW_OFF 0                                  // 32*1032*2  = 66048
#define LA_OFF 66048                              // 64*1032*2  = 132096
#define LG_OFF (66048 + 132096)                   // gs 8192
#define LSTM_SMEM (LG_OFF + 8192)                 // 206336

__global__ void __launch_bounds__(512, 1)
lstm_layer(const float* __restrict__ G,
           const __half* __restrict__ Wsp,   // [2][2048][1536] (w0|w1|w0 rows)
           const float* __restrict__ h0,
           const float* __restrict__ c0,
           __half* __restrict__ hsplit,      // [2][2][64*1024]
           float* __restrict__ Hcat,
           __half* __restrict__ Aout) {
    extern __shared__ char dsm[];
    const uint32_t sW = smem_u32(dsm) + LW_OFF;
    const uint32_t sA = smem_u32(dsm) + LA_OFF;
    float (*gs)[64][8] = reinterpret_cast<float(*)[64][8]>(dsm + LG_OFF);

    const int dir = blockIdx.y;
    const int nb = blockIdx.x;
    const int u0 = nb * 8;
    const int tid = threadIdx.x;
    const int lane = tid & 31;
    const int wid = tid >> 5;
    const int warpm = wid >> 2;          // 0..3 (16 rows each)
    const int warpn = wid & 3;           // gate

    // ---- load W slice: 32 rows x 1024 halves (w0|w1) into persistent smem ----
    {
        const __half* wsrc = Wsp + ((size_t)dir * 2048 + nb * 32) * 1536;
#pragma unroll
        for (int q = 0; q < 8; q++) {
            int id = tid + q * 512;              // 0..4095
            int r = id >> 7, c8 = id & 127;      // 128 8-half chunks per row
            uint4 v = *reinterpret_cast<const uint4*>(wsrc + (size_t)r * 1536 + c8 * 8);
            *reinterpret_cast<uint4*>(dsm + LW_OFF + (r * LWPAD2 + c8 * 8) * 2) = v;
        }
    }

    // ---- init: c->reg, split h0 into hsplit parity 0 (a0 at 0, a1 at 512) ----
    const int cb = tid >> 3;
    const int cj = tid & 7;
    float cr = c0[(size_t)dir * BB * HD + cb * HD + u0 + cj];
    {
        float hv = h0[(size_t)dir * BB * HD + cb * HD + u0 + cj];
        __half v0 = __float2half_rn(hv);
        __half v1 = __float2half_rn(hv - __half2float(v0));
        __half* hp = hsplit + ((size_t)0 * 2 + dir) * 64 * 1024 + cb * 1024;
        hp[u0 + cj] = v0;
        hp[512 + u0 + cj] = v1;
    }
    grid_barrier_dir(dir, 64);

    const int rowoff = ((lane >> 3) & 1) * 8 + (lane & 7);
    const int koffA  = (lane >> 4) * 8;
    const int brow   = warpn * 8 + (lane & 7);
    const int koffB  = ((lane >> 3) & 1) * 8;
    const int mrow   = warpm * 16 + rowoff;
    // paired-B address offsets (lanes 16-31 pick the second fragment)
    const int w01off  = (lane >> 4) * 512;       // phase 1: w0 | w1
    const int kpairoff = (lane >> 4) * 16;       // phase 2: ks | ks+1

    for (int s = 0; s < TT; s++) {
        const int t = dir ? (TT - 1 - s) : s;
        const __half* hin = hsplit + ((size_t)(s & 1) * 2 + dir) * 64 * 1024;
        __half* hout = hsplit + ((size_t)((s + 1) & 1) * 2 + dir) * 64 * 1024;

        // issue A slot (512 halves x 64 rows = 4096 8-half chunks; 8 per thread)
        auto issueA = [&](int half) {
#pragma unroll
            for (int q = 0; q < 8; q++) {
                int id = tid + q * 512;          // 0..4095
                int r = id >> 6, c8 = id & 63;   // 64 rows x 64 chunks
                cp16(sA + (uint32_t)(r * LAPAD2 + half * 512 + c8 * 8) * 2,
                     hin + (size_t)r * 1024 + half * 512 + c8 * 8);
            }
        };
        issueA(0); cp_commit();
        issueA(1); cp_commit();

        // hoisted G loads (consumed after phase 2; latency hidden by mma)
        const int j0 = (lane & 3) * 2;
        const size_t gcol = (size_t)dir * 2048 + warpn * 512 + u0 + j0;
        const int m1 = warpm * 16 + (lane >> 2);
        const int m2 = m1 + 8;
        const float2 g1 = *reinterpret_cast<const float2*>(
            &G[(size_t)(t * BB + m1) * NG + gcol]);
        const float2 g2 = *reinterpret_cast<const float2*>(
            &G[(size_t)(t * BB + m2) * NG + gcol]);

        float acc[4];
#pragma unroll
        for (int q = 0; q < 4; q++) acc[q] = 0.f;

        // phase 1: a0 ready -> acc += a0*w0 + a0*w1 (paired B ldsm4)
        cp_wait<1>();
        __syncthreads();
#pragma unroll
        for (int ks = 0; ks < 32; ks++) {
            uint32_t af[4];
            ldsm4(sA + (uint32_t)(mrow * LAPAD2 + ks * 16 + koffA) * 2, af);
            uint32_t bf[4];
            ldsm4(sW + (uint32_t)(brow * LWPAD2 + w01off + ks * 16 + koffB) * 2, bf);
            mma16816(acc, af, bf);        // w0
            mma16816(acc, af, bf + 2);    // w1
        }

        // phase 2: a1 ready -> acc += a1*w0 (B for ks,ks+1 in one ldsm4)
        cp_wait<0>();
        __syncthreads();
#pragma unroll
        for (int kp = 0; kp < 16; kp++) {
            uint32_t bf[4];
            ldsm4(sW + (uint32_t)(brow * LWPAD2 + kpairoff + kp * 32 + koffB) * 2, bf);
#pragma unroll
            for (int j = 0; j < 2; j++) {
                uint32_t af[4];
                ldsm4(sA + (uint32_t)(mrow * LAPAD2 + 512 + (kp * 2 + j) * 16 + koffA) * 2, af);
                mma16816(acc, af, bf + 2 * j);
            }
        }

        // add G and stage gates in smem (warpn == gate)
        {
            gs[warpn][m1][j0]     = acc[0] + g1.x;
            gs[warpn][m1][j0 + 1] = acc[1] + g1.y;
            gs[warpn][m2][j0]     = acc[2] + g2.x;
            gs[warpn][m2][j0 + 1] = acc[3] + g2.y;
        }
        __syncthreads();

        // cell update: thread -> (batch cb, unit cj)
        {
            float ig = gs[0][cb][cj];
            float fg = gs[1][cb][cj];
            float gg = gs[2][cb][cj];
            float og = gs[3][cb][cj];
            float si = 1.f / (1.f + expf(-ig));
            float sf = 1.f / (1.f + expf(-fg));
            float so = 1.f / (1.f + expf(-og));
            float cn = sf * cr + si * tanhf(gg);
            float hn = so * tanhf(cn);
            cr = cn;
            __half v0 = __float2half_rn(hn);
            __half v1 = __float2half_rn(hn - __half2float(v0));
            if (Aout) {
                __half* ap = Aout + (size_t)(t * BB + cb) * (3 * HH)
                                  + dir * HD + u0 + cj;
                ap[0]      = v0;
                ap[HH]     = v0;
                ap[2 * HH] = v1;
            } else {
                Hcat[(size_t)t * BB * HH + cb * HH + dir * HD + u0 + cj] = hn;
            }
            __half* hp = hout + (size_t)cb * 1024;
            hp[u0 + cj] = v0;
            hp[512 + u0 + cj] = v1;
        }
        grid_barrier_dir(dir, 64);
    }
}

// ---------------- final linear ---------------------------------------------------
__global__ void linear_feats(const float* __restrict__ H1,
                             const float* __restrict__ lw,
                             const float* __restrict__ lb,
                             float* __restrict__ feats) {
    int warp = (blockIdx.x * blockDim.x + threadIdx.x) >> 5;
    int lane = threadIdx.x & 31;
    if (warp >= MROWS) return;
    const float* hrow = H1 + (size_t)warp * HH;
    float acc[CC];
#pragma unroll
    for (int c = 0; c < CC; c++) acc[c] = 0.f;
    for (int k = lane; k < HH; k += 32) {
        float hv = hrow[k];
#pragma unroll
        for (int c = 0; c < CC; c++) acc[c] += hv * lw[c * HH + k];
    }
#pragma unroll
    for (int c = 0; c < CC; c++) {
        float v = acc[c];
#pragma unroll
        for (int o = 16; o; o >>= 1) v += __shfl_down_sync(0xffffffffu, v, o);
        if (lane == 0) {
            int t = warp >> 6, b = warp & 63;
            feats[((size_t)b * TT + t) * CC + c] = v + lb[c];
        }
    }
}

// ---------------- Viterbi decode --------------------------------------------------
__global__ void viterbi_kernel(const float* __restrict__ feats,
                               const float* __restrict__ trans,
                               float* __restrict__ out,
                               int write_scores, int write_paths, int path_off) {
    const int b = blockIdx.x;
    const int c = threadIdx.x;
    __shared__ unsigned char bp[TT][CC];

    float tr[CC];
#pragma unroll
    for (int p = 0; p < CC; p++) tr[p] = trans[c * CC + p];

    float fv = (c == START_TAG) ? 0.f : -10000.f;
    const float* f = feats + (size_t)b * TT * CC;

    for (int t = 0; t < TT; t++) {
        float best = -3.4e38f;
        int arg = 0;
#pragma unroll
        for (int p = 0; p < CC; p++) {
            float sc = __shfl_sync(0x0000ffffu, fv, p) + tr[p];
            if (sc > best) { best = sc; arg = p; }
        }
        bp[t][c] = (unsigned char)arg;
        fv = best + f[t * CC + c];
    }

    float term = fv + trans[STOP_TAG * CC + c];
    float bv = term;
    int bi = c;
#pragma unroll
    for (int o = 8; o; o >>= 1) {
        float ov = __shfl_down_sync(0x0000ffffu, bv, o);
        int oi = __shfl_down_sync(0x0000ffffu, bi, o);
        if (ov > bv || (ov == bv && oi < bi)) { bv = ov; bi = oi; }
    }
    bv = __shfl_sync(0x0000ffffu, bv, 0);
    bi = __shfl_sync(0x0000ffffu, bi, 0);

    if (c == 0) {
        if (write_scores) out[b] = bv;
        if (write_paths) {
            int tag = bi;
            for (int t = TT - 1; t >= 0; t--) {
                out[path_off + b * TT + t] = (float)tag;
                tag = bp[t][tag];
            }
        }
    }
}

// ---------------- launch -----------------------------------------------------------
extern "C" void kernel_launch(void* const* d_in, const int* in_sizes, int n_in,
                              void* d_out, int out_size) {
    const int*   sent    = (const int*)  d_in[0];
    const float* emb     = (const float*)d_in[1];
    const float* wih0    = (const float*)d_in[2];
    const float* whh0    = (const float*)d_in[3];
    const float* bih0    = (const float*)d_in[4];
    const float* bhh0    = (const float*)d_in[5];
    const float* wih1    = (const float*)d_in[6];
    const float* whh1    = (const float*)d_in[7];
    const float* bih1    = (const float*)d_in[8];
    const float* bhh1    = (const float*)d_in[9];
    const float* linw    = (const float*)d_in[10];
    const float* linb    = (const float*)d_in[11];
    const float* trans   = (const float*)d_in[12];
    const float* h0      = (const float*)d_in[13];
    const float* c0      = (const float*)d_in[14];

    float *pG, *pH1, *pfe;
    __half *pAs, *pWs, *pWh0, *pWh1, *phs;
    cudaGetSymbolAddress((void**)&pG,  g_G);
    cudaGetSymbolAddress((void**)&pH1, g_H1);
    cudaGetSymbolAddress((void**)&pfe, g_feats);
    cudaGetSymbolAddress((void**)&pAs, g_As);
    cudaGetSymbolAddress((void**)&pWs, g_Ws);
    cudaGetSymbolAddress((void**)&pWh0, g_Whsp);
    pWh1 = pWh0 + (size_t)2 * 2048 * 1536;
    cudaGetSymbolAddress((void**)&phs, g_hsplit);

    cudaFuncSetAttribute(gemm_mma, cudaFuncAttributeMaxDynamicSharedMemorySize,
                         GEMM_SMEM);
    cudaFuncSetAttribute(lstm_layer, cudaFuncAttributeMaxDynamicSharedMemorySize,
                         LSTM_SMEM);

    // 1) fused embedding gather + fp16 split -> g_As (K3 = 1536)
    embed_split_kernel<<<MROWS, 128>>>(sent, emb, pAs);

    // recurrent-weight splits
    {
        long long tWh = (long long)2 * 2048 * 512;
        splitWhh_kernel<<<(unsigned)((tWh + 255) / 256), 256>>>(whh0, pWh0);
        splitWhh_kernel<<<(unsigned)((tWh + 255) / 256), 256>>>(whh1, pWh1);
    }

    // 2) layer-0: W split + tensor GEMM (K3 = 1536)
    {
        long long tW = (long long)NG * EE;
        splitW_kernel<<<(unsigned)((tW + 255) / 256), 256>>>(wih0, pWs, EE, tW);
        gemm_mma<<<dim3(NG / BN, MROWS / BM), 256, GEMM_SMEM>>>(
            pAs, pWs, bih0, bhh0, pG, 3 * EE);
    }

    // 3) layer-0 recurrence: writes layer-1 split A directly into g_As
    lstm_layer<<<dim3(64, 2), 512, LSTM_SMEM>>>(pG, pWh0, h0, c0, phs,
                                                nullptr, pAs);

    // 4) layer-1: W split + tensor GEMM (K3 = 3072)
    {
        long long tW = (long long)NG * HH;
        splitW_kernel<<<(unsigned)((tW + 255) / 256), 256>>>(wih1, pWs, HH, tW);
        gemm_mma<<<dim3(NG / BN, MROWS / BM), 256, GEMM_SMEM>>>(
            pAs, pWs, bih1, bhh1, pG, 3 * HH);
    }

    // 5) layer-1 recurrence: writes fp32 H1 for the linear layer
    lstm_layer<<<dim3(64, 2), 512, LSTM_SMEM>>>(pG, pWh1,
                                                h0 + 2 * BB * HD, c0 + 2 * BB * HD,
                                                phs, pH1, nullptr);

    // 6) linear -> feats
    linear_feats<<<(MROWS * 32 + 255) / 256, 256>>>(pH1, linw, linb, pfe);

    // 7) Viterbi decode + output write
    float* out = (float*)d_out;
    int write_scores, write_paths, path_off;
    if (out_size >= BB + BB * TT) { write_scores = 1; write_paths = 1; path_off = BB; }
    else if (out_size == BB * TT) { write_scores = 0; write_paths = 1; path_off = 0; }
    else                          { write_scores = 1; write_paths = 0; path_off = 0; }
    viterbi_kernel<<<BB, CC>>>(pfe, trans, out, write_scores, write_paths, path_off);
}